// round 16
// baseline (speedup 1.0000x reference)
#include <cuda_runtime.h>
#include <cstdint>
#include <math.h>

#define L_SEQ 4096
#define C_DIM 768
#define NH    12
#define N_QKV 2304
#define KSPLIT 2

__device__ float    g_qkv[L_SEQ * N_QKV];      // Q in cols 0..767 (f32)
__device__ uint16_t g_kh [L_SEQ * C_DIM];
__device__ uint16_t g_kl [L_SEQ * C_DIM];
__device__ uint16_t g_vth[C_DIM * L_SEQ];
__device__ uint16_t g_vtl[C_DIM * L_SEQ];
__device__ uint16_t g_ah [L_SEQ * C_DIM];
__device__ uint16_t g_al [L_SEQ * C_DIM];
__device__ uint16_t g_xh [L_SEQ * C_DIM];
__device__ uint16_t g_xl [L_SEQ * C_DIM];
__device__ uint16_t g_wqh[C_DIM * N_QKV];
__device__ uint16_t g_wql[C_DIM * N_QKV];
__device__ uint16_t g_wph[C_DIM * C_DIM];
__device__ uint16_t g_wpl[C_DIM * C_DIM];
__device__ float    g_po [KSPLIT * L_SEQ * C_DIM];
__device__ float    g_pl [KSPLIT * NH * L_SEQ];

// ---------------- helpers ----------------
__device__ __forceinline__ uint32_t smem_u32(const void* p){
    uint32_t a; asm("{ .reg .u64 t; cvta.to.shared.u64 t, %1; cvt.u32.u64 %0, t; }":"=r"(a):"l"(p)); return a;
}
__device__ __forceinline__ void split2(float x, float y, uint32_t& h, uint32_t& l){
    uint32_t hp; asm("cvt.rn.bf16x2.f32 %0, %1, %2;" : "=r"(hp) : "f"(y), "f"(x));
    float hx = __uint_as_float(hp << 16);
    float hy = __uint_as_float(hp & 0xffff0000u);
    float lx = x - hx, ly = y - hy;
    asm("cvt.rn.bf16x2.f32 %0, %1, %2;" : "=r"(l) : "f"(ly), "f"(lx));
    h = hp;
}
__device__ __forceinline__ uint16_t bf16hi(float a){
    uint16_t r; asm("cvt.rn.bf16.f32 %0, %1;" : "=h"(r) : "f"(a)); return r;
}
__device__ __forceinline__ float bf16tof(uint16_t h){
    return __uint_as_float(((uint32_t)h) << 16);
}
__device__ __forceinline__ float ex2f(float x){
    float r; asm("ex2.approx.f32 %0, %1;" : "=f"(r) : "f"(x)); return r;
}
__device__ __forceinline__ void mma16816(float* c, uint32_t a0, uint32_t a1,
                                         uint32_t a2, uint32_t a3,
                                         uint32_t b0, uint32_t b1){
    asm volatile("mma.sync.aligned.m16n8k16.row.col.f32.bf16.bf16.f32 "
        "{%0,%1,%2,%3}, {%4,%5,%6,%7}, {%8,%9}, {%0,%1,%2,%3};"
        : "+f"(c[0]), "+f"(c[1]), "+f"(c[2]), "+f"(c[3])
        : "r"(a0), "r"(a1), "r"(a2), "r"(a3), "r"(b0), "r"(b1));
}
__device__ __forceinline__ void ldsm4(uint32_t* r, uint32_t addr){
    asm volatile("ldmatrix.sync.aligned.m8n8.x4.shared.b16 {%0,%1,%2,%3}, [%4];"
        : "=r"(r[0]), "=r"(r[1]), "=r"(r[2]), "=r"(r[3]) : "r"(addr));
}
__device__ __forceinline__ void ldsm4t(uint32_t* r, uint32_t addr){
    asm volatile("ldmatrix.sync.aligned.m8n8.x4.trans.shared.b16 {%0,%1,%2,%3}, [%4];"
        : "=r"(r[0]), "=r"(r[1]), "=r"(r[2]), "=r"(r[3]) : "r"(addr));
}
__device__ __forceinline__ void cpa16(uint32_t dst, const void* src){
    asm volatile("cp.async.cg.shared.global [%0], [%1], 16;" :: "r"(dst), "l"(src) : "memory");
}
#define CP_COMMIT() asm volatile("cp.async.commit_group;" ::: "memory")

// mbarrier helpers
#define MBAR_INIT(m,c)  asm volatile("mbarrier.init.shared.b64 [%0], %1;"::"r"(m),"r"(c):"memory")
#define MBAR_ARRIVE(m)  asm volatile("mbarrier.arrive.shared.b64 _, [%0];"::"r"(m):"memory")
#define CPA_MB_ARRIVE(m) asm volatile("cp.async.mbarrier.arrive.noinc.shared.b64 [%0];"::"r"(m):"memory")
#define MBAR_WAIT(m,p) do{ uint32_t _d; \
    asm volatile("{ .reg .pred p; mbarrier.try_wait.parity.acquire.cta.shared::cta.b64 p,[%1],%2; selp.b32 %0,1,0,p; }":"=r"(_d):"r"(m),"r"(p):"memory"); \
    if(!_d){ asm volatile("{ .reg .pred P1; W%=: mbarrier.try_wait.parity.acquire.cta.shared::cta.b64 P1,[%0],%1,0x989680; @P1 bra.uni D%=; bra.uni W%=; D%=: }"::"r"(m),"r"(p):"memory"); } }while(0)

// ---------------- prep: split all three f32 inputs -> bf16 hi/lo ----------
#define SPN1 ((L_SEQ * C_DIM) / 2)
#define SPN2 (SPN1 + (C_DIM * N_QKV) / 2)
#define SPN3 (SPN2 + (C_DIM * C_DIM) / 2)

__global__ __launch_bounds__(256) void split_all(const float* __restrict__ x,
                                                 const float* __restrict__ wq,
                                                 const float* __restrict__ wp)
{
    int i = blockIdx.x * blockDim.x + threadIdx.x;
    const float* src; uint16_t *hi, *lo; int off;
    if (i < SPN1){ src = x;  hi = g_xh;  lo = g_xl;  off = i; }
    else if (i < SPN2){ src = wq; hi = g_wqh; lo = g_wql; off = i - SPN1; }
    else if (i < SPN3){ src = wp; hi = g_wph; lo = g_wpl; off = i - SPN2; }
    else return;
    float2 v = *(const float2*)(src + 2*off);
    uint32_t h, l;
    split2(v.x, v.y, h, l);
    *(uint32_t*)(hi + 2*off) = h;
    *(uint32_t*)(lo + 2*off) = l;
}

// ---------------- combine: out = (sum_z O_z) / (sum_z l_z), pre-split ----
__global__ __launch_bounds__(256) void combine_kernel()
{
    int p = blockIdx.x * blockDim.x + threadIdx.x;
    if (p >= (L_SEQ * C_DIM) / 2) return;
    const int e = 2 * p;
    const int l = e / C_DIM;
    const int c = e % C_DIM;
    const int h = c / 64;
    float2 a = *(const float2*)&g_po[e];
    float2 b = *(const float2*)&g_po[L_SEQ * C_DIM + e];
    float ls = g_pl[(size_t)h * L_SEQ + l] + g_pl[(size_t)(NH + h) * L_SEQ + l];
    float inv = 1.f / ls;
    uint32_t hh, ll;
    split2((a.x + b.x) * inv, (a.y + b.y) * inv, hh, ll);
    *(uint32_t*)&g_ah[e] = hh;
    *(uint32_t*)&g_al[e] = ll;
}

// =====================================================================
// Pure-bf16 GEMM with 3-buffer mbarrier deferred-refill pipeline
// (unchanged from R15).
// =====================================================================
#define APITCH 80
#define BPITCH 272
#define ASZ (128 * APITCH)
#define BSZ (32 * BPITCH)
#define GBUF (2*ASZ + 2*BSZ)
#define GEMM_SMEM (3 * GBUF + 64)

template<int MODE>
__global__ __launch_bounds__(256, 2) void gemm_bf16(
    const uint16_t* __restrict__ Agh, const uint16_t* __restrict__ Agl,
    const uint16_t* __restrict__ Bgh, const uint16_t* __restrict__ Bgl,
    const float* __restrict__ bias, float* __restrict__ Cmat,
    int M, int N, int K)
{
    extern __shared__ char smc[];
    const uint32_t sb = smem_u32(smc);
    const uint32_t mb = sb + 3 * GBUF;

    const int tid = threadIdx.x, w = tid >> 5, lane = tid & 31;
    const int wm = w & 3, wn = w >> 2;
    const int g = lane >> 2, tig = lane & 3;
    const int m0 = blockIdx.y * 128, n0 = blockIdx.x * 128;

    float acc[2][8][4];
#pragma unroll
    for (int mt = 0; mt < 2; mt++)
#pragma unroll
        for (int nt = 0; nt < 8; nt++)
#pragma unroll
            for (int e = 0; e < 4; e++) acc[mt][nt][e] = 0.f;

    const int ac0 = tid * 2;
    const int ar  = ac0 >> 2, acc4 = ac0 & 3;
    const int br  = ac0 >> 4, bcc  = ac0 & 15;

    auto issue = [&](int k0, int buf){
        const uint32_t bbase = sb + (uint32_t)buf * GBUF;
        const size_t asrc = (size_t)(m0 + ar) * K + k0 + acc4 * 8;
        const size_t bsrc = (size_t)(k0 + br) * N + n0 + bcc * 8;
#pragma unroll
        for (int i = 0; i < 2; i++){
            const uint32_t adst = bbase + (uint32_t)ar * APITCH + (acc4 + i) * 16;
            cpa16(adst,       Agh + asrc + i*8);
            cpa16(adst + ASZ, Agl + asrc + i*8);
            const uint32_t bdst = bbase + 2*ASZ + (uint32_t)br * BPITCH + (bcc + i) * 16;
            cpa16(bdst,       Bgh + bsrc + i*8);
            cpa16(bdst + BSZ, Bgl + bsrc + i*8);
        }
    };

    if (tid == 0){
#pragma unroll
        for (int b = 0; b < 3; b++){
            MBAR_INIT(mb + 8*b, 256);
            MBAR_INIT(mb + 24 + 8*b, 256);
        }
    }
    __syncthreads();

    const uint32_t lsel = (uint32_t)(lane & 15);
    const uint32_t lhi  = (uint32_t)(lane >> 4) * 16;

    const int NK = K / 32;
    issue(0, 0);  CPA_MB_ARRIVE(mb + 0);
    issue(32, 1); CPA_MB_ARRIVE(mb + 8);

    uint32_t fbits = 0, ebits = 0;

    for (int ki = 0; ki < NK; ki++){
        const int b = ki % 3;
        MBAR_WAIT(mb + 8*b, (fbits >> b) & 1); fbits ^= 1u << b;

        const uint32_t bbase = sb + (uint32_t)b * GBUF;
        const uint32_t AH = bbase, AL = bbase + ASZ;
        const uint32_t BH = bbase + 2*ASZ, BL = bbase + 2*ASZ + BSZ;

#pragma unroll
        for (int kt = 0; kt < 2; kt++){
            uint32_t ah[2][4], al[2][4];
#pragma unroll
            for (int mt = 0; mt < 2; mt++){
                const uint32_t aadr = (uint32_t)(wm*32 + mt*16) * APITCH
                                    + lsel * APITCH + (uint32_t)kt*32 + lhi;
                ldsm4(ah[mt], AH + aadr);
                ldsm4(al[mt], AL + aadr);
            }
#pragma unroll
            for (int nt = 0; nt < 4; nt++){
                uint32_t bh[4], bl[4];
                const uint32_t badr = ((uint32_t)kt*16 + lsel) * BPITCH
                                    + (uint32_t)wn*128 + (uint32_t)nt*32 + lhi;
                ldsm4t(bh, BH + badr);
                ldsm4t(bl, BL + badr);
#pragma unroll
                for (int mt = 0; mt < 2; mt++){
#pragma unroll
                    for (int s = 0; s < 2; s++){
                        float* c = acc[mt][nt*2 + s];
                        mma16816(c, ah[mt][0],ah[mt][1],ah[mt][2],ah[mt][3], bh[2*s], bh[2*s+1]);
                        mma16816(c, al[mt][0],al[mt][1],al[mt][2],al[mt][3], bh[2*s], bh[2*s+1]);
                        mma16816(c, ah[mt][0],ah[mt][1],ah[mt][2],ah[mt][3], bl[2*s], bl[2*s+1]);
                    }
                }
            }
        }

        MBAR_ARRIVE(mb + 24 + 8*b);

        if (ki + 2 < NK){
            const int tb = (ki + 2) % 3;
            if (ki >= 1){ MBAR_WAIT(mb + 24 + 8*tb, (ebits >> tb) & 1); ebits ^= 1u << tb; }
            issue((ki + 2) * 32, tb);
            CPA_MB_ARRIVE(mb + 8*tb);
        }
    }

#pragma unroll
    for (int mt = 0; mt < 2; mt++){
        const int row = m0 + wm*32 + mt*16 + g;
#pragma unroll
        for (int nt = 0; nt < 8; nt++){
            const int col = n0 + wn*64 + nt*8 + 2*tig;
            float c0 = acc[mt][nt][0], c1 = acc[mt][nt][1];
            float c2 = acc[mt][nt][2], c3 = acc[mt][nt][3];
            if (MODE == 1){
                c0 += bias[col]; c1 += bias[col+1];
                c2 += bias[col]; c3 += bias[col+1];
                *(float2*)&Cmat[(size_t)row * N + col]     = make_float2(c0, c1);
                *(float2*)&Cmat[(size_t)(row+8) * N + col] = make_float2(c2, c3);
            } else {
                if (col < 768){
                    *(float2*)&Cmat[(size_t)row * N + col]     = make_float2(c0, c1);
                    *(float2*)&Cmat[(size_t)(row+8) * N + col] = make_float2(c2, c3);
                } else if (col < 1536){
                    const int kc = col - 768;
                    uint32_t h01, l01, h23, l23;
                    split2(c0, c1, h01, l01);
                    split2(c2, c3, h23, l23);
                    *(uint32_t*)&g_kh[(size_t)row * C_DIM + kc]     = h01;
                    *(uint32_t*)&g_kl[(size_t)row * C_DIM + kc]     = l01;
                    *(uint32_t*)&g_kh[(size_t)(row+8) * C_DIM + kc] = h23;
                    *(uint32_t*)&g_kl[(size_t)(row+8) * C_DIM + kc] = l23;
                } else {
                    const int d0 = col - 1536;
                    uint16_t h, l;
                    h = bf16hi(c0); l = bf16hi(c0 - bf16tof(h));
                    g_vth[(size_t)d0 * L_SEQ + row] = h;
                    g_vtl[(size_t)d0 * L_SEQ + row] = l;
                    h = bf16hi(c1); l = bf16hi(c1 - bf16tof(h));
                    g_vth[(size_t)(d0+1) * L_SEQ + row] = h;
                    g_vtl[(size_t)(d0+1) * L_SEQ + row] = l;
                    h = bf16hi(c2); l = bf16hi(c2 - bf16tof(h));
                    g_vth[(size_t)d0 * L_SEQ + row + 8] = h;
                    g_vtl[(size_t)d0 * L_SEQ + row + 8] = l;
                    h = bf16hi(c3); l = bf16hi(c3 - bf16tof(h));
                    g_vth[(size_t)(d0+1) * L_SEQ + row + 8] = h;
                    g_vtl[(size_t)(d0+1) * L_SEQ + row + 8] = l;
                }
            }
        }
    }
}

// =====================================================================
// Attention (split-K) with CROSS-HALF SOFTWARE PIPELINING:
// per step: P = exp/split(S_prev); S = MMA1(next half); O += P @ V(cur).
// All intra-warp dependencies get a full phase of slack.
// =====================================================================
#define TPITCH 144
#define TBYTES (64 * TPITCH)
#define BUFB   (4 * TBYTES)
#define ATT_SMEM (3 * BUFB + 64)
#define JBLK (64 / KSPLIT)

// MMA1 of (buffer base kbb, half) into S, chunked K-fragment loads (8 regs)
#define ATT_MMA1(kbb, half_, S_) do{                                          \
    const uint32_t _KH = (kbb), _KL = (kbb) + TBYTES;                         \
    _Pragma("unroll")                                                         \
    for (int t = 0; t < 4; t++){                                              \
        _Pragma("unroll")                                                     \
        for (int e = 0; e < 4; e++) S_[t][e] = 0.f;                           \
        const uint32_t base = (uint32_t)((half_)*4 + t) * 8 * TPITCH          \
                            + lrow + lmat;                                    \
        _Pragma("unroll")                                                     \
        for (int c = 0; c < 2; c++){                                          \
            uint32_t bh[4], bl[4];                                            \
            ldsm4(bh, _KH + base + (uint32_t)c*64);                           \
            ldsm4(bl, _KL + base + (uint32_t)c*64);                           \
            _Pragma("unroll")                                                 \
            for (int kt = 0; kt < 2; kt++){                                   \
                const int qk = c*2 + kt;                                      \
                mma16816(S_[t], qh[qk][0],qh[qk][1],qh[qk][2],qh[qk][3],      \
                         bh[2*kt], bh[2*kt+1]);                               \
                mma16816(S_[t], ql[qk][0],ql[qk][1],ql[qk][2],ql[qk][3],      \
                         bh[2*kt], bh[2*kt+1]);                               \
                mma16816(S_[t], qh[qk][0],qh[qk][1],qh[qk][2],qh[qk][3],      \
                         bl[2*kt], bl[2*kt+1]);                               \
            }                                                                 \
        }                                                                     \
    }                                                                         \
}while(0)

__global__ __launch_bounds__(256, 2) void attn_mma(const float* __restrict__ qkv)
{
    extern __shared__ char smc[];
    const uint32_t sb = smem_u32(smc);
    const uint32_t mb = sb + 3 * BUFB;

    const int tid = threadIdx.x, w = tid >> 5, lane = tid & 31;
    const int g = lane >> 2, tig = lane & 3;
    const int h = blockIdx.y, m0 = blockIdx.x * 128, hoff = h * 64;
    const int z = blockIdx.z, j0 = z * JBLK;
    const int r0 = m0 + w * 16 + g;

    const int sr = tid >> 2;
    const int cb = (tid & 3) * 2;

    auto issue = [&](int j, int buf){
        const uint32_t dst = sb + (uint32_t)buf * BUFB + (uint32_t)sr * TPITCH;
        const size_t krow = (size_t)(j*64 + sr) * C_DIM + hoff;
        const size_t vrow = (size_t)(hoff + sr) * L_SEQ + j*64;
#pragma unroll
        for (int c = cb; c < cb + 2; c++){
            cpa16(dst            + c*16, g_kh  + krow + c*8);
            cpa16(dst +   TBYTES + c*16, g_kl  + krow + c*8);
            cpa16(dst + 2*TBYTES + c*16, g_vth + vrow + c*8);
            cpa16(dst + 3*TBYTES + c*16, g_vtl + vrow + c*8);
        }
    };

    if (tid == 0){
#pragma unroll
        for (int b = 0; b < 3; b++){
            MBAR_INIT(mb + 8*b, 256);
            MBAR_INIT(mb + 24 + 8*b, 256);
        }
    }
    __syncthreads();

    const float QSC = 0.125f * 1.4426950408889634f;
    uint32_t qh[4][4], ql[4][4];
#pragma unroll
    for (int kt = 0; kt < 4; kt++){
        const float* q0 = qkv + (size_t)r0       * N_QKV + hoff + kt*16;
        const float* q1 = qkv + (size_t)(r0 + 8) * N_QKV + hoff + kt*16;
        float2 x0 = *(const float2*)(q0 + 2*tig);
        float2 x1 = *(const float2*)(q1 + 2*tig);
        float2 x2 = *(const float2*)(q0 + 8 + 2*tig);
        float2 x3 = *(const float2*)(q1 + 8 + 2*tig);
        split2(x0.x*QSC, x0.y*QSC, qh[kt][0], ql[kt][0]);
        split2(x1.x*QSC, x1.y*QSC, qh[kt][1], ql[kt][1]);
        split2(x2.x*QSC, x2.y*QSC, qh[kt][2], ql[kt][2]);
        split2(x3.x*QSC, x3.y*QSC, qh[kt][3], ql[kt][3]);
    }

    float O[8][4];
#pragma unroll
    for (int t = 0; t < 8; t++)
#pragma unroll
        for (int e = 0; e < 4; e++) O[t][e] = 0.f;
    float lsum0 = 0.f, lsum1 = 0.f;

    const uint32_t lrow = (uint32_t)(lane & 7) * TPITCH;
    const uint32_t lmat = (uint32_t)(lane >> 3) * 16;

    issue(j0 + 0, 0); CPA_MB_ARRIVE(mb + 0);
    issue(j0 + 1, 1); CPA_MB_ARRIVE(mb + 8);

    uint32_t fbits = 0, ebits = 0;
    const int worder = w & 1;

    // ---- prologue: wait buffer0, S = MMA1(block j0, half worder) ----
    float S[4][4];
    MBAR_WAIT(mb + 0, 0); fbits ^= 1u;
    ATT_MMA1(sb, worder, S);

    for (int jj = 0; jj < JBLK; jj++){
        const int b = jj % 3;
        const uint32_t bb = sb + (uint32_t)b * BUFB;

#pragma unroll
        for (int hh = 0; hh < 2; hh++){
            const int half = hh ^ worder;

            // ---- P = exp/split(S)  (inputs ready since previous step) ----
            uint32_t ph[2][4], pl[2][4];
#pragma unroll
            for (int t = 0; t < 4; t++){
#pragma unroll
                for (int e = 0; e < 4; e++) S[t][e] = ex2f(S[t][e]);
                lsum0 += S[t][0] + S[t][1];
                lsum1 += S[t][2] + S[t][3];
            }
#pragma unroll
            for (int kt = 0; kt < 2; kt++){
                split2(S[2*kt][0],   S[2*kt][1],   ph[kt][0], pl[kt][0]);
                split2(S[2*kt][2],   S[2*kt][3],   ph[kt][1], pl[kt][1]);
                split2(S[2*kt+1][0], S[2*kt+1][1], ph[kt][2], pl[kt][2]);
                split2(S[2*kt+1][2], S[2*kt+1][3], ph[kt][3], pl[kt][3]);
            }

            // ---- S = MMA1(next half)  (independent of P) ----
            const int ns = jj*2 + hh + 1;
            if (ns < 2*JBLK){
                const int njj = ns >> 1;
                const int nb = njj % 3;
                if ((ns & 1) == 0){ MBAR_WAIT(mb + 8*nb, (fbits >> nb) & 1); fbits ^= 1u << nb; }
                const int nhalf = (ns & 1) ^ worder;
                ATT_MMA1(sb + (uint32_t)nb * BUFB, nhalf, S);
            }

            // ---- MMA2: O += P @ V(current half)  (P ready) ----
            {
                const uint32_t VH = bb + 2*TBYTES, VL = bb + 3*TBYTES;
#pragma unroll
                for (int t = 0; t < 8; t++){
                    uint32_t bh[4], bl[4];
                    const uint32_t base = (uint32_t)t * 8 * TPITCH + lrow + lmat
                                        + (uint32_t)half * 64;
                    ldsm4(bh, VH + base);
                    ldsm4(bl, VL + base);
#pragma unroll
                    for (int kt = 0; kt < 2; kt++){
                        mma16816(O[t], ph[kt][0],ph[kt][1],ph[kt][2],ph[kt][3], bh[2*kt], bh[2*kt+1]);
                        mma16816(O[t], pl[kt][0],pl[kt][1],pl[kt][2],pl[kt][3], bh[2*kt], bh[2*kt+1]);
                        mma16816(O[t], ph[kt][0],ph[kt][1],ph[kt][2],ph[kt][3], bl[2*kt], bl[2*kt+1]);
                    }
                }
            }
        }

        MBAR_ARRIVE(mb + 24 + 8*b);

        if (jj + 2 < JBLK){
            const int tb = (jj + 2) % 3;
            if (jj >= 1){ MBAR_WAIT(mb + 24 + 8*tb, (ebits >> tb) & 1); ebits ^= 1u << tb; }
            issue(j0 + jj + 2, tb);
            CPA_MB_ARRIVE(mb + 8*tb);
        }
    }

    // ---- epilogue: unnormalized partial O (fp32) + partial lsum ----
    lsum0 += __shfl_xor_sync(0xffffffffu, lsum0, 1);
    lsum0 += __shfl_xor_sync(0xffffffffu, lsum0, 2);
    lsum1 += __shfl_xor_sync(0xffffffffu, lsum1, 1);
    lsum1 += __shfl_xor_sync(0xffffffffu, lsum1, 2);

    float* po = g_po + (size_t)z * L_SEQ * C_DIM;
#pragma unroll
    for (int t = 0; t < 8; t++){
        const size_t c0 = (size_t)r0       * C_DIM + hoff + 8*t + 2*tig;
        const size_t c1 = (size_t)(r0 + 8) * C_DIM + hoff + 8*t + 2*tig;
        *(float2*)&po[c0] = make_float2(O[t][0], O[t][1]);
        *(float2*)&po[c1] = make_float2(O[t][2], O[t][3]);
    }
    if (tig == 0){
        g_pl[(size_t)(z * NH + h) * L_SEQ + r0]     = lsum0;
        g_pl[(size_t)(z * NH + h) * L_SEQ + r0 + 8] = lsum1;
    }
}

// ---------------------------------------------------------------------------
extern "C" void kernel_launch(void* const* d_in, const int* in_sizes, int n_in,
                              void* d_out, int out_size)
{
    const float* x      = (const float*)d_in[0];
    const float* w_qkv  = (const float*)d_in[1];
    const float* w_proj = (const float*)d_in[2];
    const float* b_proj = (const float*)d_in[3];
    float* out = (float*)d_out;

    float* qkv_p = nullptr;
    cudaGetSymbolAddress((void**)&qkv_p, g_qkv);
    uint16_t *xh, *xl, *wqh, *wql, *wph, *wpl, *ah, *al;
    cudaGetSymbolAddress((void**)&xh,  g_xh);  cudaGetSymbolAddress((void**)&xl,  g_xl);
    cudaGetSymbolAddress((void**)&wqh, g_wqh); cudaGetSymbolAddress((void**)&wql, g_wql);
    cudaGetSymbolAddress((void**)&wph, g_wph); cudaGetSymbolAddress((void**)&wpl, g_wpl);
    cudaGetSymbolAddress((void**)&ah,  g_ah);  cudaGetSymbolAddress((void**)&al,  g_al);

    static bool cfg = false;
    if (!cfg){
        cudaFuncSetAttribute(attn_mma,
            cudaFuncAttributeMaxDynamicSharedMemorySize, ATT_SMEM);
        cudaFuncSetAttribute(gemm_bf16<1>,
            cudaFuncAttributeMaxDynamicSharedMemorySize, GEMM_SMEM);
        cudaFuncSetAttribute(gemm_bf16<2>,
            cudaFuncAttributeMaxDynamicSharedMemorySize, GEMM_SMEM);
        cfg = true;
    }

    // 0) pre-split inputs (single launch)
    split_all<<<(SPN3 + 255)/256, 256>>>(x, w_qkv, w_proj);

    // 1) QKV projection
    dim3 g1(N_QKV/128, L_SEQ/128);
    gemm_bf16<2><<<g1, 256, GEMM_SMEM>>>(xh, xl, wqh, wql, nullptr, qkv_p,
                                         L_SEQ, N_QKV, C_DIM);

    // 2) split-K attention -> partials
    dim3 g2(L_SEQ/128, NH, KSPLIT);
    attn_mma<<<g2, 256, ATT_SMEM>>>(qkv_p);

    // 2b) combine partials -> pre-split proj operand
    combine_kernel<<<(L_SEQ*C_DIM/2 + 255)/256, 256>>>();

    // 3) output projection + bias
    dim3 g3(C_DIM/128, L_SEQ/128);
    gemm_bf16<1><<<g3, 256, GEMM_SMEM>>>(ah, al, wph, wpl, b_proj, out,
                                         L_SEQ, C_DIM, C_DIM);
}

// round 17
// speedup vs baseline: 1.7594x; 1.7594x over previous
#include <cuda_runtime.h>
#include <cstdint>
#include <math.h>

#define L_SEQ 4096
#define C_DIM 768
#define NH    12
#define N_QKV 2304
#define KSPLIT 2

__device__ float    g_qkv[L_SEQ * N_QKV];      // Q in cols 0..767 (f32)
__device__ uint16_t g_kf [L_SEQ * C_DIM];      // K fp16 [l][h*64+d]
__device__ uint16_t g_vtf[C_DIM * L_SEQ];      // V^T fp16 [h*64+d][l]
__device__ uint16_t g_ah [L_SEQ * C_DIM];      // attention out hi/lo (proj A, bf16 split)
__device__ uint16_t g_al [L_SEQ * C_DIM];
__device__ uint16_t g_xh [L_SEQ * C_DIM];
__device__ uint16_t g_xl [L_SEQ * C_DIM];
__device__ uint16_t g_wqh[C_DIM * N_QKV];
__device__ uint16_t g_wql[C_DIM * N_QKV];
__device__ uint16_t g_wph[C_DIM * C_DIM];
__device__ uint16_t g_wpl[C_DIM * C_DIM];
__device__ float    g_po [KSPLIT * L_SEQ * C_DIM];
__device__ float    g_pl [KSPLIT * NH * L_SEQ];

// ---------------- helpers ----------------
__device__ __forceinline__ uint32_t smem_u32(const void* p){
    uint32_t a; asm("{ .reg .u64 t; cvta.to.shared.u64 t, %1; cvt.u32.u64 %0, t; }":"=r"(a):"l"(p)); return a;
}
__device__ __forceinline__ void split2(float x, float y, uint32_t& h, uint32_t& l){
    uint32_t hp; asm("cvt.rn.bf16x2.f32 %0, %1, %2;" : "=r"(hp) : "f"(y), "f"(x));
    float hx = __uint_as_float(hp << 16);
    float hy = __uint_as_float(hp & 0xffff0000u);
    float lx = x - hx, ly = y - hy;
    asm("cvt.rn.bf16x2.f32 %0, %1, %2;" : "=r"(l) : "f"(ly), "f"(lx));
    h = hp;
}
__device__ __forceinline__ uint16_t bf16hi(float a){
    uint16_t r; asm("cvt.rn.bf16.f32 %0, %1;" : "=h"(r) : "f"(a)); return r;
}
__device__ __forceinline__ float bf16tof(uint16_t h){
    return __uint_as_float(((uint32_t)h) << 16);
}
__device__ __forceinline__ uint32_t f16x2(float x, float y){  // x -> low, y -> high
    uint32_t r; asm("cvt.rn.f16x2.f32 %0, %1, %2;" : "=r"(r) : "f"(y), "f"(x)); return r;
}
__device__ __forceinline__ uint16_t f16h(float a){
    uint16_t r; asm("cvt.rn.f16.f32 %0, %1;" : "=h"(r) : "f"(a)); return r;
}
__device__ __forceinline__ float ex2f(float x){
    float r; asm("ex2.approx.f32 %0, %1;" : "=f"(r) : "f"(x)); return r;
}
__device__ __forceinline__ void mma16816(float* c, uint32_t a0, uint32_t a1,
                                         uint32_t a2, uint32_t a3,
                                         uint32_t b0, uint32_t b1){
    asm volatile("mma.sync.aligned.m16n8k16.row.col.f32.bf16.bf16.f32 "
        "{%0,%1,%2,%3}, {%4,%5,%6,%7}, {%8,%9}, {%0,%1,%2,%3};"
        : "+f"(c[0]), "+f"(c[1]), "+f"(c[2]), "+f"(c[3])
        : "r"(a0), "r"(a1), "r"(a2), "r"(a3), "r"(b0), "r"(b1));
}
__device__ __forceinline__ void mma16816h(float* c, uint32_t a0, uint32_t a1,
                                          uint32_t a2, uint32_t a3,
                                          uint32_t b0, uint32_t b1){
    asm volatile("mma.sync.aligned.m16n8k16.row.col.f32.f16.f16.f32 "
        "{%0,%1,%2,%3}, {%4,%5,%6,%7}, {%8,%9}, {%0,%1,%2,%3};"
        : "+f"(c[0]), "+f"(c[1]), "+f"(c[2]), "+f"(c[3])
        : "r"(a0), "r"(a1), "r"(a2), "r"(a3), "r"(b0), "r"(b1));
}
__device__ __forceinline__ void ldsm4(uint32_t* r, uint32_t addr){
    asm volatile("ldmatrix.sync.aligned.m8n8.x4.shared.b16 {%0,%1,%2,%3}, [%4];"
        : "=r"(r[0]), "=r"(r[1]), "=r"(r[2]), "=r"(r[3]) : "r"(addr));
}
__device__ __forceinline__ void ldsm4t(uint32_t* r, uint32_t addr){
    asm volatile("ldmatrix.sync.aligned.m8n8.x4.trans.shared.b16 {%0,%1,%2,%3}, [%4];"
        : "=r"(r[0]), "=r"(r[1]), "=r"(r[2]), "=r"(r[3]) : "r"(addr));
}
__device__ __forceinline__ void cpa16(uint32_t dst, const void* src){
    asm volatile("cp.async.cg.shared.global [%0], [%1], 16;" :: "r"(dst), "l"(src) : "memory");
}
#define CP_COMMIT() asm volatile("cp.async.commit_group;" ::: "memory")

// mbarrier helpers
#define MBAR_INIT(m,c)  asm volatile("mbarrier.init.shared.b64 [%0], %1;"::"r"(m),"r"(c):"memory")
#define MBAR_ARRIVE(m)  asm volatile("mbarrier.arrive.shared.b64 _, [%0];"::"r"(m):"memory")
#define CPA_MB_ARRIVE(m) asm volatile("cp.async.mbarrier.arrive.noinc.shared.b64 [%0];"::"r"(m):"memory")
#define MBAR_WAIT(m,p) do{ uint32_t _d; \
    asm volatile("{ .reg .pred p; mbarrier.try_wait.parity.acquire.cta.shared::cta.b64 p,[%1],%2; selp.b32 %0,1,0,p; }":"=r"(_d):"r"(m),"r"(p):"memory"); \
    if(!_d){ asm volatile("{ .reg .pred P1; W%=: mbarrier.try_wait.parity.acquire.cta.shared::cta.b64 P1,[%0],%1,0x989680; @P1 bra.uni D%=; bra.uni W%=; D%=: }"::"r"(m),"r"(p):"memory"); } }while(0)

// ---------------- prep: split all three f32 inputs -> bf16 hi/lo ----------
#define SPN1 ((L_SEQ * C_DIM) / 2)
#define SPN2 (SPN1 + (C_DIM * N_QKV) / 2)
#define SPN3 (SPN2 + (C_DIM * C_DIM) / 2)

__global__ __launch_bounds__(256) void split_all(const float* __restrict__ x,
                                                 const float* __restrict__ wq,
                                                 const float* __restrict__ wp)
{
    int i = blockIdx.x * blockDim.x + threadIdx.x;
    const float* src; uint16_t *hi, *lo; int off;
    if (i < SPN1){ src = x;  hi = g_xh;  lo = g_xl;  off = i; }
    else if (i < SPN2){ src = wq; hi = g_wqh; lo = g_wql; off = i - SPN1; }
    else if (i < SPN3){ src = wp; hi = g_wph; lo = g_wpl; off = i - SPN2; }
    else return;
    float2 v = *(const float2*)(src + 2*off);
    uint32_t h, l;
    split2(v.x, v.y, h, l);
    *(uint32_t*)(hi + 2*off) = h;
    *(uint32_t*)(lo + 2*off) = l;
}

// ---------------- combine: out = (sum_z O_z) / (sum_z l_z), pre-split ----
__global__ __launch_bounds__(256) void combine_kernel()
{
    int p = blockIdx.x * blockDim.x + threadIdx.x;
    if (p >= (L_SEQ * C_DIM) / 2) return;
    const int e = 2 * p;
    const int l = e / C_DIM;
    const int c = e % C_DIM;
    const int h = c / 64;
    float2 a = *(const float2*)&g_po[e];
    float2 b = *(const float2*)&g_po[L_SEQ * C_DIM + e];
    float ls = g_pl[(size_t)h * L_SEQ + l] + g_pl[(size_t)(NH + h) * L_SEQ + l];
    float inv = 1.f / ls;
    uint32_t hh, ll;
    split2((a.x + b.x) * inv, (a.y + b.y) * inv, hh, ll);
    *(uint32_t*)&g_ah[e] = hh;
    *(uint32_t*)&g_al[e] = ll;
}

// =====================================================================
// Pure-bf16 GEMM with 3-buffer mbarrier deferred-refill pipeline
// (R15, unchanged except K/V epilogue now emits plain fp16).
// =====================================================================
#define APITCH 80
#define BPITCH 272
#define ASZ (128 * APITCH)
#define BSZ (32 * BPITCH)
#define GBUF (2*ASZ + 2*BSZ)
#define GEMM_SMEM (3 * GBUF + 64)

template<int MODE>
__global__ __launch_bounds__(256, 2) void gemm_bf16(
    const uint16_t* __restrict__ Agh, const uint16_t* __restrict__ Agl,
    const uint16_t* __restrict__ Bgh, const uint16_t* __restrict__ Bgl,
    const float* __restrict__ bias, float* __restrict__ Cmat,
    int M, int N, int K)
{
    extern __shared__ char smc[];
    const uint32_t sb = smem_u32(smc);
    const uint32_t mb = sb + 3 * GBUF;

    const int tid = threadIdx.x, w = tid >> 5, lane = tid & 31;
    const int wm = w & 3, wn = w >> 2;
    const int g = lane >> 2, tig = lane & 3;
    const int m0 = blockIdx.y * 128, n0 = blockIdx.x * 128;

    float acc[2][8][4];
#pragma unroll
    for (int mt = 0; mt < 2; mt++)
#pragma unroll
        for (int nt = 0; nt < 8; nt++)
#pragma unroll
            for (int e = 0; e < 4; e++) acc[mt][nt][e] = 0.f;

    const int ac0 = tid * 2;
    const int ar  = ac0 >> 2, acc4 = ac0 & 3;
    const int br  = ac0 >> 4, bcc  = ac0 & 15;

    auto issue = [&](int k0, int buf){
        const uint32_t bbase = sb + (uint32_t)buf * GBUF;
        const size_t asrc = (size_t)(m0 + ar) * K + k0 + acc4 * 8;
        const size_t bsrc = (size_t)(k0 + br) * N + n0 + bcc * 8;
#pragma unroll
        for (int i = 0; i < 2; i++){
            const uint32_t adst = bbase + (uint32_t)ar * APITCH + (acc4 + i) * 16;
            cpa16(adst,       Agh + asrc + i*8);
            cpa16(adst + ASZ, Agl + asrc + i*8);
            const uint32_t bdst = bbase + 2*ASZ + (uint32_t)br * BPITCH + (bcc + i) * 16;
            cpa16(bdst,       Bgh + bsrc + i*8);
            cpa16(bdst + BSZ, Bgl + bsrc + i*8);
        }
    };

    if (tid == 0){
#pragma unroll
        for (int b = 0; b < 3; b++){
            MBAR_INIT(mb + 8*b, 256);
            MBAR_INIT(mb + 24 + 8*b, 256);
        }
    }
    __syncthreads();

    const uint32_t lsel = (uint32_t)(lane & 15);
    const uint32_t lhi  = (uint32_t)(lane >> 4) * 16;

    const int NK = K / 32;
    issue(0, 0);  CPA_MB_ARRIVE(mb + 0);
    issue(32, 1); CPA_MB_ARRIVE(mb + 8);

    uint32_t fbits = 0, ebits = 0;

    for (int ki = 0; ki < NK; ki++){
        const int b = ki % 3;
        MBAR_WAIT(mb + 8*b, (fbits >> b) & 1); fbits ^= 1u << b;

        const uint32_t bbase = sb + (uint32_t)b * GBUF;
        const uint32_t AH = bbase, AL = bbase + ASZ;
        const uint32_t BH = bbase + 2*ASZ, BL = bbase + 2*ASZ + BSZ;

#pragma unroll
        for (int kt = 0; kt < 2; kt++){
            uint32_t ah[2][4], al[2][4];
#pragma unroll
            for (int mt = 0; mt < 2; mt++){
                const uint32_t aadr = (uint32_t)(wm*32 + mt*16) * APITCH
                                    + lsel * APITCH + (uint32_t)kt*32 + lhi;
                ldsm4(ah[mt], AH + aadr);
                ldsm4(al[mt], AL + aadr);
            }
#pragma unroll
            for (int nt = 0; nt < 4; nt++){
                uint32_t bh[4], bl[4];
                const uint32_t badr = ((uint32_t)kt*16 + lsel) * BPITCH
                                    + (uint32_t)wn*128 + (uint32_t)nt*32 + lhi;
                ldsm4t(bh, BH + badr);
                ldsm4t(bl, BL + badr);
#pragma unroll
                for (int mt = 0; mt < 2; mt++){
#pragma unroll
                    for (int s = 0; s < 2; s++){
                        float* c = acc[mt][nt*2 + s];
                        mma16816(c, ah[mt][0],ah[mt][1],ah[mt][2],ah[mt][3], bh[2*s], bh[2*s+1]);
                        mma16816(c, al[mt][0],al[mt][1],al[mt][2],al[mt][3], bh[2*s], bh[2*s+1]);
                        mma16816(c, ah[mt][0],ah[mt][1],ah[mt][2],ah[mt][3], bl[2*s], bl[2*s+1]);
                    }
                }
            }
        }

        MBAR_ARRIVE(mb + 24 + 8*b);

        if (ki + 2 < NK){
            const int tb = (ki + 2) % 3;
            if (ki >= 1){ MBAR_WAIT(mb + 24 + 8*tb, (ebits >> tb) & 1); ebits ^= 1u << tb; }
            issue((ki + 2) * 32, tb);
            CPA_MB_ARRIVE(mb + 8*tb);
        }
    }

#pragma unroll
    for (int mt = 0; mt < 2; mt++){
        const int row = m0 + wm*32 + mt*16 + g;
#pragma unroll
        for (int nt = 0; nt < 8; nt++){
            const int col = n0 + wn*64 + nt*8 + 2*tig;
            float c0 = acc[mt][nt][0], c1 = acc[mt][nt][1];
            float c2 = acc[mt][nt][2], c3 = acc[mt][nt][3];
            if (MODE == 1){
                c0 += bias[col]; c1 += bias[col+1];
                c2 += bias[col]; c3 += bias[col+1];
                *(float2*)&Cmat[(size_t)row * N + col]     = make_float2(c0, c1);
                *(float2*)&Cmat[(size_t)(row+8) * N + col] = make_float2(c2, c3);
            } else {
                if (col < 768){
                    *(float2*)&Cmat[(size_t)row * N + col]     = make_float2(c0, c1);
                    *(float2*)&Cmat[(size_t)(row+8) * N + col] = make_float2(c2, c3);
                } else if (col < 1536){                 // K: plain fp16
                    const int kc = col - 768;
                    *(uint32_t*)&g_kf[(size_t)row * C_DIM + kc]     = f16x2(c0, c1);
                    *(uint32_t*)&g_kf[(size_t)(row+8) * C_DIM + kc] = f16x2(c2, c3);
                } else {                                // V: plain fp16, transposed
                    const int d0 = col - 1536;
                    g_vtf[(size_t)d0     * L_SEQ + row]     = f16h(c0);
                    g_vtf[(size_t)(d0+1) * L_SEQ + row]     = f16h(c1);
                    g_vtf[(size_t)d0     * L_SEQ + row + 8] = f16h(c2);
                    g_vtf[(size_t)(d0+1) * L_SEQ + row + 8] = f16h(c3);
                }
            }
        }
    }
}

// =====================================================================
// Attention (split-K, R15 loop structure) with SINGLE-TERM fp16 MMAs.
// Buffers: K tile (64x64 fp16) + V tile per stage = 18.4 KB.
// =====================================================================
#define TPITCH 144
#define TBYTES (64 * TPITCH)
#define BUFB   (2 * TBYTES)          // K + V
#define ATT_SMEM (3 * BUFB + 64)     // 55360
#define JBLK (64 / KSPLIT)

__global__ __launch_bounds__(256, 2) void attn_mma(const float* __restrict__ qkv)
{
    extern __shared__ char smc[];
    const uint32_t sb = smem_u32(smc);
    const uint32_t mb = sb + 3 * BUFB;

    const int tid = threadIdx.x, w = tid >> 5, lane = tid & 31;
    const int g = lane >> 2, tig = lane & 3;
    const int h = blockIdx.y, m0 = blockIdx.x * 128, hoff = h * 64;
    const int z = blockIdx.z, j0 = z * JBLK;
    const int r0 = m0 + w * 16 + g;

    const int sr = tid >> 2;
    const int cb = (tid & 3) * 2;

    auto issue = [&](int j, int buf){
        const uint32_t dst = sb + (uint32_t)buf * BUFB + (uint32_t)sr * TPITCH;
        const size_t krow = (size_t)(j*64 + sr) * C_DIM + hoff;
        const size_t vrow = (size_t)(hoff + sr) * L_SEQ + j*64;
#pragma unroll
        for (int c = cb; c < cb + 2; c++){
            cpa16(dst          + c*16, g_kf  + krow + c*8);
            cpa16(dst + TBYTES + c*16, g_vtf + vrow + c*8);
        }
    };

    if (tid == 0){
#pragma unroll
        for (int b = 0; b < 3; b++){
            MBAR_INIT(mb + 8*b, 256);
            MBAR_INIT(mb + 24 + 8*b, 256);
        }
    }
    __syncthreads();

    // ---- Q fragments (fp16, scaled by 0.125*log2e) ----
    const float QSC = 0.125f * 1.4426950408889634f;
    uint32_t qf[4][4];
#pragma unroll
    for (int kt = 0; kt < 4; kt++){
        const float* q0 = qkv + (size_t)r0       * N_QKV + hoff + kt*16;
        const float* q1 = qkv + (size_t)(r0 + 8) * N_QKV + hoff + kt*16;
        float2 x0 = *(const float2*)(q0 + 2*tig);
        float2 x1 = *(const float2*)(q1 + 2*tig);
        float2 x2 = *(const float2*)(q0 + 8 + 2*tig);
        float2 x3 = *(const float2*)(q1 + 8 + 2*tig);
        qf[kt][0] = f16x2(x0.x*QSC, x0.y*QSC);
        qf[kt][1] = f16x2(x1.x*QSC, x1.y*QSC);
        qf[kt][2] = f16x2(x2.x*QSC, x2.y*QSC);
        qf[kt][3] = f16x2(x3.x*QSC, x3.y*QSC);
    }

    float O[8][4];
#pragma unroll
    for (int t = 0; t < 8; t++)
#pragma unroll
        for (int e = 0; e < 4; e++) O[t][e] = 0.f;
    float lsum0 = 0.f, lsum1 = 0.f;

    const uint32_t lrow = (uint32_t)(lane & 7) * TPITCH;
    const uint32_t lmat = (uint32_t)(lane >> 3) * 16;

    issue(j0 + 0, 0); CPA_MB_ARRIVE(mb + 0);
    issue(j0 + 1, 1); CPA_MB_ARRIVE(mb + 8);

    uint32_t fbits = 0, ebits = 0;
    const int worder = w & 1;

    for (int jj = 0; jj < JBLK; jj++){
        const int b = jj % 3;
        MBAR_WAIT(mb + 8*b, (fbits >> b) & 1); fbits ^= 1u << b;

        const uint32_t bb = sb + (uint32_t)b * BUFB;
        const uint32_t KH = bb, VH = bb + TBYTES;

#pragma unroll
        for (int hh = 0; hh < 2; hh++){
            const int half = hh ^ worder;

            // ---- MMA1: S(half) = Q @ K(half)^T, single term fp16 ----
            float S[4][4];
#pragma unroll
            for (int t = 0; t < 4; t++){
#pragma unroll
                for (int e = 0; e < 4; e++) S[t][e] = 0.f;
                uint32_t bh[8];
                const uint32_t base = (uint32_t)(half*4 + t) * 8 * TPITCH + lrow + lmat;
                ldsm4(bh,     KH + base);
                ldsm4(bh + 4, KH + base + 64);
#pragma unroll
                for (int kt = 0; kt < 4; kt++)
                    mma16816h(S[t], qf[kt][0],qf[kt][1],qf[kt][2],qf[kt][3],
                              bh[2*kt], bh[2*kt+1]);
            }

            // ---- softmax: P = 2^S, pack fp16 ----
            uint32_t pf[2][4];
#pragma unroll
            for (int t = 0; t < 4; t++){
#pragma unroll
                for (int e = 0; e < 4; e++) S[t][e] = ex2f(S[t][e]);
                lsum0 += S[t][0] + S[t][1];
                lsum1 += S[t][2] + S[t][3];
            }
#pragma unroll
            for (int kt = 0; kt < 2; kt++){
                pf[kt][0] = f16x2(S[2*kt][0],   S[2*kt][1]);
                pf[kt][1] = f16x2(S[2*kt][2],   S[2*kt][3]);
                pf[kt][2] = f16x2(S[2*kt+1][0], S[2*kt+1][1]);
                pf[kt][3] = f16x2(S[2*kt+1][2], S[2*kt+1][3]);
            }

            // ---- MMA2: O += P(half) @ V(half), single term fp16 ----
#pragma unroll
            for (int t = 0; t < 8; t++){
                uint32_t bh[4];
                const uint32_t base = (uint32_t)t * 8 * TPITCH + lrow + lmat
                                    + (uint32_t)half * 64;
                ldsm4(bh, VH + base);
#pragma unroll
                for (int kt = 0; kt < 2; kt++)
                    mma16816h(O[t], pf[kt][0],pf[kt][1],pf[kt][2],pf[kt][3],
                              bh[2*kt], bh[2*kt+1]);
            }
        }

        MBAR_ARRIVE(mb + 24 + 8*b);

        if (jj + 2 < JBLK){
            const int tb = (jj + 2) % 3;
            if (jj >= 1){ MBAR_WAIT(mb + 24 + 8*tb, (ebits >> tb) & 1); ebits ^= 1u << tb; }
            issue(j0 + jj + 2, tb);
            CPA_MB_ARRIVE(mb + 8*tb);
        }
    }

    // ---- epilogue: unnormalized partial O (fp32) + partial lsum ----
    lsum0 += __shfl_xor_sync(0xffffffffu, lsum0, 1);
    lsum0 += __shfl_xor_sync(0xffffffffu, lsum0, 2);
    lsum1 += __shfl_xor_sync(0xffffffffu, lsum1, 1);
    lsum1 += __shfl_xor_sync(0xffffffffu, lsum1, 2);

    float* po = g_po + (size_t)z * L_SEQ * C_DIM;
#pragma unroll
    for (int t = 0; t < 8; t++){
        const size_t c0 = (size_t)r0       * C_DIM + hoff + 8*t + 2*tig;
        const size_t c1 = (size_t)(r0 + 8) * C_DIM + hoff + 8*t + 2*tig;
        *(float2*)&po[c0] = make_float2(O[t][0], O[t][1]);
        *(float2*)&po[c1] = make_float2(O[t][2], O[t][3]);
    }
    if (tig == 0){
        g_pl[(size_t)(z * NH + h) * L_SEQ + r0]     = lsum0;
        g_pl[(size_t)(z * NH + h) * L_SEQ + r0 + 8] = lsum1;
    }
}

// ---------------------------------------------------------------------------
extern "C" void kernel_launch(void* const* d_in, const int* in_sizes, int n_in,
                              void* d_out, int out_size)
{
    const float* x      = (const float*)d_in[0];
    const float* w_qkv  = (const float*)d_in[1];
    const float* w_proj = (const float*)d_in[2];
    const float* b_proj = (const float*)d_in[3];
    float* out = (float*)d_out;

    float* qkv_p = nullptr;
    cudaGetSymbolAddress((void**)&qkv_p, g_qkv);
    uint16_t *xh, *xl, *wqh, *wql, *wph, *wpl, *ah, *al;
    cudaGetSymbolAddress((void**)&xh,  g_xh);  cudaGetSymbolAddress((void**)&xl,  g_xl);
    cudaGetSymbolAddress((void**)&wqh, g_wqh); cudaGetSymbolAddress((void**)&wql, g_wql);
    cudaGetSymbolAddress((void**)&wph, g_wph); cudaGetSymbolAddress((void**)&wpl, g_wpl);
    cudaGetSymbolAddress((void**)&ah,  g_ah);  cudaGetSymbolAddress((void**)&al,  g_al);

    static bool cfg = false;
    if (!cfg){
        cudaFuncSetAttribute(attn_mma,
            cudaFuncAttributeMaxDynamicSharedMemorySize, ATT_SMEM);
        cudaFuncSetAttribute(gemm_bf16<1>,
            cudaFuncAttributeMaxDynamicSharedMemorySize, GEMM_SMEM);
        cudaFuncSetAttribute(gemm_bf16<2>,
            cudaFuncAttributeMaxDynamicSharedMemorySize, GEMM_SMEM);
        cfg = true;
    }

    // 0) pre-split inputs (single launch)
    split_all<<<(SPN3 + 255)/256, 256>>>(x, w_qkv, w_proj);

    // 1) QKV projection
    dim3 g1(N_QKV/128, L_SEQ/128);
    gemm_bf16<2><<<g1, 256, GEMM_SMEM>>>(xh, xl, wqh, wql, nullptr, qkv_p,
                                         L_SEQ, N_QKV, C_DIM);

    // 2) split-K attention -> partials
    dim3 g2(L_SEQ/128, NH, KSPLIT);
    attn_mma<<<g2, 256, ATT_SMEM>>>(qkv_p);

    // 2b) combine partials -> pre-split proj operand
    combine_kernel<<<(L_SEQ*C_DIM/2 + 255)/256, 256>>>();

    // 3) output projection + bias
    dim3 g3(C_DIM/128, L_SEQ/128);
    gemm_bf16<1><<<g3, 256, GEMM_SMEM>>>(ah, al, wph, wpl, b_proj, out,
                                         L_SEQ, C_DIM, C_DIM);
}